// round 3
// baseline (speedup 1.0000x reference)
#include <cuda_runtime.h>

#define BB 8
#define NX 32
#define DD 128
#define KK 256
#define HH 2
#define SROW 260   // padded smem row stride (floats) for score kernel

typedef unsigned long long ull;

__device__ float d_Hbuf[3][BB][NX][KK];     // relu(in@W^T+b) for x,y,z
__device__ float d_blocksum[BB][HH][NX];    // partial exp-sums per (b,h,x)
__device__ float d_partial[BB][NX][KK];     // logits partials per (b,x)
__device__ float d_logits[BB][KK];
__device__ int   d_cnt_b[BB];
__device__ int   d_cnt_all;

__device__ __forceinline__ float warp_sum(float v){
#pragma unroll
  for (int o = 16; o > 0; o >>= 1) v += __shfl_xor_sync(0xffffffffu, v, o);
  return v;
}

// ---- packed f32x2 helpers ----
__device__ __forceinline__ ull pk2(float lo, float hi){
  ull r; asm("mov.b64 %0, {%1,%2};" : "=l"(r) : "f"(lo), "f"(hi)); return r;
}
__device__ __forceinline__ void fma2(ull& d, ull a, ull b){
  asm("fma.rn.f32x2 %0, %1, %2, %0;" : "+l"(d) : "l"(a), "l"(b));
}
__device__ __forceinline__ ull mul2(ull a, ull b){
  ull r; asm("mul.rn.f32x2 %0, %1, %2;" : "=l"(r) : "l"(a), "l"(b)); return r;
}
__device__ __forceinline__ ull add2(ull a, ull b){
  ull r; asm("add.rn.f32x2 %0, %1, %2;" : "=l"(r) : "l"(a), "l"(b)); return r;
}
__device__ __forceinline__ float hsum2(ull a){
  float lo, hi; asm("mov.b64 {%0,%1}, %2;" : "=f"(lo), "=f"(hi) : "l"(a)); return lo + hi;
}

// ---------------- K1: projections with inline weight-norm ----------------
// grid 192 = b(8) x t(3) x g(8 groups of 4 rows); 512 thr = rh(2) x k(256), 2 rows/thread
__global__ void __launch_bounds__(512) proj_kernel(
    const float* __restrict__ x, const float* __restrict__ y, const float* __restrict__ z,
    const float* __restrict__ Vx, const float* __restrict__ Vy, const float* __restrict__ Vz,
    const float* __restrict__ bx, const float* __restrict__ by, const float* __restrict__ bz,
    const float* __restrict__ gx, const float* __restrict__ gy, const float* __restrict__ gz){
  int id = blockIdx.x;
  int b = id / 24; int rem = id % 24; int t = rem >> 3; int g = rem & 7;
  const float* in   = (t==0)?x :(t==1)?y :z;
  const float* V    = (t==0)?Vx:(t==1)?Vy:Vz;
  const float* bias = (t==0)?bx:(t==1)?by:bz;
  const float* gs   = (t==0)?gx:(t==1)?gy:gz;
  __shared__ float4 srow[4][32];
  __shared__ float  red[16];
  __shared__ float  sscale;
  int tid = threadIdx.x;
  int rh = tid >> 8, k = tid & 255;
  for (int i = tid; i < 128; i += 512){
    int rr = i >> 5, dd = i & 31;
    srow[rr][dd] = reinterpret_cast<const float4*>(in + (size_t)(b*NX + g*4 + rr)*DD)[dd];
  }
  __syncthreads();
  const float4* Vr = reinterpret_cast<const float4*>(V + (size_t)k * DD);
  const float4* s0 = &srow[rh*2][0];
  const float4* s1 = &srow[rh*2+1][0];
  float a0 = 0.f, a1 = 0.f, vsq = 0.f;
#pragma unroll 8
  for (int d = 0; d < 32; d++){
    float4 v = Vr[d];
    vsq = fmaf(v.x,v.x, fmaf(v.y,v.y, fmaf(v.z,v.z, fmaf(v.w,v.w, vsq))));
    float4 p0 = s0[d], p1 = s1[d];
    a0 += v.x*p0.x + v.y*p0.y + v.z*p0.z + v.w*p0.w;
    a1 += v.x*p1.x + v.y*p1.y + v.z*p1.z + v.w*p1.w;
  }
  vsq = warp_sum(vsq);
  if ((tid & 31) == 0) red[tid >> 5] = vsq;
  __syncthreads();
  if (tid < 32){
    float v = (tid < 16) ? red[tid] : 0.f;
    v = warp_sum(v);
    if (tid == 0) sscale = gs[0] * rsqrtf(v * 0.5f);   // each k row counted twice
  }
  __syncthreads();
  float sc = sscale, bk = bias[k];
  int row = g*4 + rh*2;
  d_Hbuf[t][b][row][k]   = fmaxf(fmaf(a0, sc, bk), 0.f);
  d_Hbuf[t][b][row+1][k] = fmaxf(fmaf(a1, sc, bk), 0.f);
}

// ---------------- K2: scores -> exp (shift=0) -> partial sums; 1 x per block, k split in halves ----------------
__global__ void __launch_bounds__(512) score_kernel(const float* __restrict__ Vh,
                                                    const float* __restrict__ gh,
                                                    const float* __restrict__ bh,
                                                    float* __restrict__ gatt){
  extern __shared__ float sm[];
  float* sy   = sm;                   // 32 rows, stride SROW
  float* sz   = sm + 32*SROW;
  float* sa   = sm + 64*SROW;         // [h][256]
  float* sps  = sa + 512;             // [8][512] half-partials
  float* sred = sps + 4096;           // 32
  float* ssc  = sred + 32;            // 1
  int xg = blockIdx.x, b = blockIdx.y;
  int tid = threadIdx.x;
  int kh = tid >> 8, t = tid & 255;

  const float4* Hy4 = reinterpret_cast<const float4*>(&d_Hbuf[1][b][0][0]);
  const float4* Hz4 = reinterpret_cast<const float4*>(&d_Hbuf[2][b][0][0]);
  for (int i = tid; i < 2048; i += 512){
    int row = i >> 6, col = i & 63;
    reinterpret_cast<float4*>(sy + row*SROW)[col] = Hy4[i];
    reinterpret_cast<float4*>(sz + row*SROW)[col] = Hz4[i];
  }
  { // ||Vh||_F over 512 elems, one per thread
    float v = Vh[tid];
    float s = warp_sum(v * v);
    if ((tid & 31) == 0) sred[tid >> 5] = s;
  }
  __syncthreads();
  if (tid == 0){
    float s = 0.f;
#pragma unroll
    for (int i = 0; i < 16; i++) s += sred[i];
    ssc[0] = gh[0] * rsqrtf(s);
  }
  __syncthreads();
  sa[tid] = d_Hbuf[0][b][xg][t] * ssc[0] * Vh[tid];   // tid = h*256 + k
  __syncthreads();

  int yq = t >> 3, zq = t & 7;
  const float4* a04  = reinterpret_cast<const float4*>(sa) + kh*32;
  const float4* a14  = reinterpret_cast<const float4*>(sa + 256) + kh*32;
  const float4* yrow = reinterpret_cast<const float4*>(sy + yq*SROW) + kh*32;
  const float4* z0r  = reinterpret_cast<const float4*>(sz + (zq +  0)*SROW) + kh*32;
  const float4* z1r  = reinterpret_cast<const float4*>(sz + (zq +  8)*SROW) + kh*32;
  const float4* z2r  = reinterpret_cast<const float4*>(sz + (zq + 16)*SROW) + kh*32;
  const float4* z3r  = reinterpret_cast<const float4*>(sz + (zq + 24)*SROW) + kh*32;

  ull A00=0ull,A01=0ull,A02=0ull,A03=0ull,A10=0ull,A11=0ull,A12=0ull,A13=0ull;
#pragma unroll 4
  for (int kb = 0; kb < 32; kb++){
    float4 a0 = a04[kb], a1 = a14[kb], yv = yrow[kb];
    float4 zv0 = z0r[kb], zv1 = z1r[kb], zv2 = z2r[kb], zv3 = z3r[kb];
    ull yp = pk2(yv.x, yv.y), yq2 = pk2(yv.z, yv.w);
    ull p0p = mul2(pk2(a0.x, a0.y), yp),  p0q = mul2(pk2(a0.z, a0.w), yq2);
    ull p1p = mul2(pk2(a1.x, a1.y), yp),  p1q = mul2(pk2(a1.z, a1.w), yq2);
    ull z0p = pk2(zv0.x, zv0.y), z0q = pk2(zv0.z, zv0.w);
    ull z1p = pk2(zv1.x, zv1.y), z1q = pk2(zv1.z, zv1.w);
    ull z2p = pk2(zv2.x, zv2.y), z2q = pk2(zv2.z, zv2.w);
    ull z3p = pk2(zv3.x, zv3.y), z3q = pk2(zv3.z, zv3.w);
    fma2(A00, p0p, z0p); fma2(A01, p0p, z1p); fma2(A02, p0p, z2p); fma2(A03, p0p, z3p);
    fma2(A10, p1p, z0p); fma2(A11, p1p, z1p); fma2(A12, p1p, z2p); fma2(A13, p1p, z3p);
    fma2(A00, p0q, z0q); fma2(A01, p0q, z1q); fma2(A02, p0q, z2q); fma2(A03, p0q, z3q);
    fma2(A10, p1q, z0q); fma2(A11, p1q, z1q); fma2(A12, p1q, z2q); fma2(A13, p1q, z3q);
  }
  float p[8];
  p[0]=hsum2(A00); p[1]=hsum2(A01); p[2]=hsum2(A02); p[3]=hsum2(A03);
  p[4]=hsum2(A10); p[5]=hsum2(A11); p[6]=hsum2(A12); p[7]=hsum2(A13);
#pragma unroll
  for (int i = 0; i < 8; i++) sps[i*512 + tid] = p[i];
  __syncthreads();
  if (kh == 0){
    float b0 = bh[0], b1 = bh[1];
    float e[8];
#pragma unroll
    for (int i = 0; i < 8; i++)
      e[i] = __expf(p[i] + sps[i*512 + 256 + t] + ((i < 4) ? b0 : b1));
    size_t base0 = ((size_t)(b*HH + 0)*NX + xg)*1024 + yq*32 + zq;
    size_t base1 = ((size_t)(b*HH + 1)*NX + xg)*1024 + yq*32 + zq;
    gatt[base0 +  0] = e[0]; gatt[base0 +  8] = e[1]; gatt[base0 + 16] = e[2]; gatt[base0 + 24] = e[3];
    gatt[base1 +  0] = e[4]; gatt[base1 +  8] = e[5]; gatt[base1 + 16] = e[6]; gatt[base1 + 24] = e[7];
    float ls0 = e[0]+e[1]+e[2]+e[3], ls1 = e[4]+e[5]+e[6]+e[7];
    ls0 = warp_sum(ls0); ls1 = warp_sum(ls1);
    int wid = tid >> 5;    // 0..7
    if ((tid & 31) == 0){ sred[wid] = ls0; sred[8 + wid] = ls1; }
  }
  __syncthreads();
  if (tid < 2){
    float s = 0.f;
#pragma unroll
    for (int w = 0; w < 8; w++) s += sred[tid*8 + w];
    d_blocksum[b][tid][xg] = s;
  }
}

// ---------------- K3: normalize att + logits partials + last-block reduce + BN ----------------
__global__ void __launch_bounds__(512) finalize_kernel(float* __restrict__ gatt,
                                                       const float* __restrict__ gamma,
                                                       const float* __restrict__ beta,
                                                       float* __restrict__ out){
  extern __shared__ float sm[];
  float* sy = sm;              // 8192
  float* sz = sm + 8192;       // 8192
  float* w  = sm + 16384;      // 1024 (att0+att1)
  float* vb = sm + 17408;      // 512
  float* sS = sm + 17920;      // 2
  __shared__ int flag1, flag2;
  int xg = blockIdx.x, b = blockIdx.y;
  int tid = threadIdx.x;
  int yh = tid >> 8, k = tid & 255;

  if (tid < 64){
    int h = tid >> 5, lane = tid & 31;
    float v = d_blocksum[b][h][lane];
    v = warp_sum(v);
    if (lane == 0) sS[h] = 1.f / v;
  }
  const float4* Hy4 = reinterpret_cast<const float4*>(&d_Hbuf[1][b][0][0]);
  const float4* Hz4 = reinterpret_cast<const float4*>(&d_Hbuf[2][b][0][0]);
  float4* sy4 = reinterpret_cast<float4*>(sy);
  float4* sz4 = reinterpret_cast<float4*>(sz);
  for (int i = tid; i < 2048; i += 512){ sy4[i] = Hy4[i]; sz4[i] = Hz4[i]; }
  float xk = d_Hbuf[0][b][xg][k];
  __syncthreads();

  { // normalize att in place + build w = att0+att1 (float2 per thread, 1024 floats total)
    float invS0 = sS[0], invS1 = sS[1];
    float2* g0 = reinterpret_cast<float2*>(gatt + ((size_t)(b*HH + 0)*NX + xg)*1024);
    float2* g1 = reinterpret_cast<float2*>(gatt + ((size_t)(b*HH + 1)*NX + xg)*1024);
    float2 e0 = g0[tid], e1 = g1[tid];
    float2 n0, n1, wv;
    n0.x = e0.x*invS0; n0.y = e0.y*invS0;
    n1.x = e1.x*invS1; n1.y = e1.y*invS1;
    wv.x = n0.x + n1.x; wv.y = n0.y + n1.y;
    g0[tid] = n0; g1[tid] = n1;
    reinterpret_cast<float2*>(w)[tid] = wv;
  }
  __syncthreads();

  ull zk2[16];
#pragma unroll
  for (int zp = 0; zp < 16; zp++)
    zk2[zp] = pk2(sz[(2*zp)*256 + k], sz[(2*zp+1)*256 + k]);

  float v = 0.f;
#pragma unroll 4
  for (int j = 0; j < 16; j++){
    int yy = yh*16 + j;
    const float4* wr = reinterpret_cast<const float4*>(w + yy*32);
    ull t2a = 0ull, t2b = 0ull;
#pragma unroll
    for (int q = 0; q < 8; q++){
      float4 wv = wr[q];
      fma2(t2a, pk2(wv.x, wv.y), zk2[2*q]);
      fma2(t2b, pk2(wv.z, wv.w), zk2[2*q+1]);
    }
    v = fmaf(sy[yy*256 + k], hsum2(add2(t2a, t2b)), v);
  }
  vb[tid] = v;
  __syncthreads();
  if (tid < 256) d_partial[b][xg][k] = xk * (vb[tid] + vb[tid + 256]);
  __threadfence();
  if (tid == 0){
    int old = atomicAdd(&d_cnt_b[b], 1);
    flag1 = (old == 31);
  }
  __syncthreads();
  if (flag1){
    __threadfence();
    { // deterministic x-reduction for this b
      int xh = tid >> 8, kk = tid & 255;
      float s = 0.f;
#pragma unroll
      for (int i = 0; i < 16; i++) s += d_partial[b][xh*16 + i][kk];
      vb[tid] = s;
    }
    __syncthreads();
    if (tid < 256) d_logits[b][tid] = vb[tid] + vb[tid + 256];
    __threadfence();
    __syncthreads();
    if (tid == 0){
      __threadfence();
      int o2 = atomicAdd(&d_cnt_all, 1);
      flag2 = (o2 == 7);
    }
    __syncthreads();
    if (flag2){
      __threadfence();
      if (tid < 256){
        int kk = tid;
        float l[8];
        float mean = 0.f;
#pragma unroll
        for (int b2 = 0; b2 < 8; b2++){ l[b2] = d_logits[b2][kk]; mean += l[b2]; }
        mean *= 0.125f;
        float var = 0.f;
#pragma unroll
        for (int b2 = 0; b2 < 8; b2++){ float d = l[b2] - mean; var = fmaf(d, d, var); }
        var *= 0.125f;
        float inv = rsqrtf(var + 1e-5f);
        float ga = gamma[kk], be = beta[kk];
#pragma unroll
        for (int b2 = 0; b2 < 8; b2++) out[b2*KK + kk] = (l[b2] - mean) * inv * ga + be;
      }
      if (tid == 0){            // reset counters for the next graph replay
        d_cnt_all = 0;
#pragma unroll
        for (int i = 0; i < 8; i++) d_cnt_b[i] = 0;
      }
    }
  }
}

extern "C" void kernel_launch(void* const* d_in, const int* in_sizes, int n_in,
                              void* d_out, int out_size){
  const float* x     = (const float*)d_in[0];
  const float* y     = (const float*)d_in[1];
  const float* z     = (const float*)d_in[2];
  const float* Vx    = (const float*)d_in[3];
  const float* gx    = (const float*)d_in[4];
  const float* bx    = (const float*)d_in[5];
  const float* Vy    = (const float*)d_in[6];
  const float* gy    = (const float*)d_in[7];
  const float* by    = (const float*)d_in[8];
  const float* Vz    = (const float*)d_in[9];
  const float* gz    = (const float*)d_in[10];
  const float* bz    = (const float*)d_in[11];
  const float* Vh    = (const float*)d_in[12];
  const float* gh    = (const float*)d_in[13];
  const float* bh    = (const float*)d_in[14];
  const float* gamma = (const float*)d_in[15];
  const float* beta  = (const float*)d_in[16];

  float* out = (float*)d_out;        // (out [8,256], att [8,2,32,32,32]) flattened in order
  float* att = out + BB*KK;

  const int SMEM2 = (64*SROW + 512 + 4096 + 32 + 4) * (int)sizeof(float);
  const int SMEM3 = (8192 + 8192 + 1024 + 512 + 2 + 6) * (int)sizeof(float);
  cudaFuncSetAttribute(score_kernel,    cudaFuncAttributeMaxDynamicSharedMemorySize, SMEM2);
  cudaFuncSetAttribute(finalize_kernel, cudaFuncAttributeMaxDynamicSharedMemorySize, SMEM3);

  proj_kernel<<<192, 512>>>(x, y, z, Vx, Vy, Vz, bx, by, bz, gx, gy, gz);
  score_kernel<<<dim3(NX, BB), 512, SMEM2>>>(Vh, gh, bh, att);
  finalize_kernel<<<dim3(NX, BB), 512, SMEM3>>>(att, gamma, beta, out);
}

// round 4
// speedup vs baseline: 1.2303x; 1.2303x over previous
#include <cuda_runtime.h>

#define BB 8
#define NX 32
#define DD 128
#define KK 256
#define HH 2
#define SROW 260   // padded smem row stride (floats) for score kernel

typedef unsigned long long ull;

__device__ float d_scales[4];
__device__ float d_Hbuf[3][BB][NX][KK];     // relu(in@W^T+b) for x,y,z
__device__ float d_blocksum[BB][HH][NX];    // partial exp-sums per (b,h,x)
__device__ float d_partial[BB][NX][KK];     // logits partials per (b,x)
__device__ float d_logits[BB][KK];
__device__ int   d_cnt_b[BB];
__device__ int   d_cnt_all;

__device__ __forceinline__ float warp_sum(float v){
#pragma unroll
  for (int o = 16; o > 0; o >>= 1) v += __shfl_xor_sync(0xffffffffu, v, o);
  return v;
}

// ---- packed f32x2 helpers ----
__device__ __forceinline__ ull pk2(float lo, float hi){
  ull r; asm("mov.b64 %0, {%1,%2};" : "=l"(r) : "f"(lo), "f"(hi)); return r;
}
__device__ __forceinline__ void fma2(ull& d, ull a, ull b){
  asm("fma.rn.f32x2 %0, %1, %2, %0;" : "+l"(d) : "l"(a), "l"(b));
}
__device__ __forceinline__ ull mul2(ull a, ull b){
  ull r; asm("mul.rn.f32x2 %0, %1, %2;" : "=l"(r) : "l"(a), "l"(b)); return r;
}
__device__ __forceinline__ ull add2(ull a, ull b){
  ull r; asm("add.rn.f32x2 %0, %1, %2;" : "=l"(r) : "l"(a), "l"(b)); return r;
}
__device__ __forceinline__ float hsum2(ull a){
  float lo, hi; asm("mov.b64 {%0,%1}, %2;" : "=f"(lo), "=f"(hi) : "l"(a)); return lo + hi;
}

// ---------------- K0: weight-norm scales g/||V||_F ----------------
__global__ void scale_kernel(const float* __restrict__ Vx, const float* __restrict__ Vy,
                             const float* __restrict__ Vz, const float* __restrict__ Vh,
                             const float* __restrict__ gx, const float* __restrict__ gy,
                             const float* __restrict__ gz, const float* __restrict__ gh){
  int i = blockIdx.x;
  const float* V = (i==0)?Vx:(i==1)?Vy:(i==2)?Vz:Vh;
  const float* g = (i==0)?gx:(i==1)?gy:(i==2)?gz:gh;
  int n = (i==3) ? (HH*KK) : (KK*DD);
  float s = 0.f;
  for (int j = threadIdx.x*4; j < n; j += blockDim.x*4){
    float4 v = reinterpret_cast<const float4*>(V)[j>>2];
    s = fmaf(v.x,v.x, fmaf(v.y,v.y, fmaf(v.z,v.z, fmaf(v.w,v.w, s))));
  }
  __shared__ float red[8];
  s = warp_sum(s);
  if ((threadIdx.x & 31) == 0) red[threadIdx.x >> 5] = s;
  __syncthreads();
  if (threadIdx.x < 32){
    float v = (threadIdx.x < 8) ? red[threadIdx.x] : 0.f;
    v = warp_sum(v);
    if (threadIdx.x == 0) d_scales[i] = g[0] * rsqrtf(v);
  }
}

// ---------------- K1: projections; 8 rows/thread, grid 96 ----------------
__global__ void __launch_bounds__(256, 1) proj_kernel(
    const float* __restrict__ x, const float* __restrict__ y, const float* __restrict__ z,
    const float* __restrict__ Vx, const float* __restrict__ Vy, const float* __restrict__ Vz,
    const float* __restrict__ bx, const float* __restrict__ by, const float* __restrict__ bz){
  int id = blockIdx.x;               // 96 = b(8) x t(3) x g(4 groups of 8 rows)
  int b = id / 12; int rem = id % 12; int t = rem >> 2; int g = rem & 3;
  const float* in   = (t==0)?x :(t==1)?y :z;
  const float* V    = (t==0)?Vx:(t==1)?Vy:Vz;
  const float* bias = (t==0)?bx:(t==1)?by:bz;
  float scale = d_scales[t];
  __shared__ float4 srow[8][32];
  int row0 = g * 8;
  for (int i = threadIdx.x; i < 256; i += 256){
    int rr = i >> 5, dd = i & 31;
    srow[rr][dd] = reinterpret_cast<const float4*>(in + (size_t)(b*NX + row0 + rr)*DD)[dd];
  }
  __syncthreads();
  int k = threadIdx.x;
  const float4* Vr = reinterpret_cast<const float4*>(V + (size_t)k * DD);
  float acc[8];
#pragma unroll
  for (int r = 0; r < 8; r++) acc[r] = 0.f;
#pragma unroll 4
  for (int d = 0; d < 32; d++){
    float4 v = Vr[d];
#pragma unroll
    for (int r = 0; r < 8; r++){
      float4 p = srow[r][d];
      acc[r] += v.x*p.x + v.y*p.y + v.z*p.z + v.w*p.w;
    }
  }
  float bk = bias[k];
#pragma unroll
  for (int r = 0; r < 8; r++)
    d_Hbuf[t][b][row0 + r][k] = fmaxf(fmaf(acc[r], scale, bk), 0.f);
}

// ---------------- K2: scores -> exp (shift=0) -> partial sums; 2 x per block ----------------
__global__ void __launch_bounds__(512) score_kernel(const float* __restrict__ Vh,
                                                    const float* __restrict__ bh,
                                                    float* __restrict__ gatt){
  extern __shared__ float sm[];
  float* sy   = sm;                  // 32 rows, stride SROW
  float* sz   = sm + 32*SROW;
  float* sa   = sm + 64*SROW;        // [half][h][256]
  float* sred = sa + 1024;           // 32
  int b = blockIdx.y;
  int half = threadIdx.x >> 8;
  int xg = blockIdx.x*2 + half;
  int t = threadIdx.x & 255;

  const float4* Hy4 = reinterpret_cast<const float4*>(&d_Hbuf[1][b][0][0]);
  const float4* Hz4 = reinterpret_cast<const float4*>(&d_Hbuf[2][b][0][0]);
  for (int i = threadIdx.x; i < 2048; i += 512){
    int row = i >> 6, col = i & 63;
    reinterpret_cast<float4*>(sy + row*SROW)[col] = Hy4[i];
    reinterpret_cast<float4*>(sz + row*SROW)[col] = Hz4[i];
  }
  {
    float sh = d_scales[3];
    float xv = d_Hbuf[0][b][xg][t];
    sa[half*512 + t]       = xv * sh * Vh[t];
    sa[half*512 + 256 + t] = xv * sh * Vh[KK + t];
  }
  __syncthreads();

  int yq = t >> 3, zq = t & 7;
  const float4* a04  = reinterpret_cast<const float4*>(sa + half*512);
  const float4* a14  = reinterpret_cast<const float4*>(sa + half*512 + 256);
  const float4* yrow = reinterpret_cast<const float4*>(sy + yq*SROW);
  const float4* z0r  = reinterpret_cast<const float4*>(sz + (zq +  0)*SROW);
  const float4* z1r  = reinterpret_cast<const float4*>(sz + (zq +  8)*SROW);
  const float4* z2r  = reinterpret_cast<const float4*>(sz + (zq + 16)*SROW);
  const float4* z3r  = reinterpret_cast<const float4*>(sz + (zq + 24)*SROW);

  ull A00=0ull,A01=0ull,A02=0ull,A03=0ull,A10=0ull,A11=0ull,A12=0ull,A13=0ull;
#pragma unroll 4
  for (int kb = 0; kb < 64; kb++){
    float4 a0 = a04[kb], a1 = a14[kb], yv = yrow[kb];
    float4 zv0 = z0r[kb], zv1 = z1r[kb], zv2 = z2r[kb], zv3 = z3r[kb];
    ull yp = pk2(yv.x, yv.y), yq2 = pk2(yv.z, yv.w);
    ull p0p = mul2(pk2(a0.x, a0.y), yp),  p0q = mul2(pk2(a0.z, a0.w), yq2);
    ull p1p = mul2(pk2(a1.x, a1.y), yp),  p1q = mul2(pk2(a1.z, a1.w), yq2);
    ull z0p = pk2(zv0.x, zv0.y), z0q = pk2(zv0.z, zv0.w);
    ull z1p = pk2(zv1.x, zv1.y), z1q = pk2(zv1.z, zv1.w);
    ull z2p = pk2(zv2.x, zv2.y), z2q = pk2(zv2.z, zv2.w);
    ull z3p = pk2(zv3.x, zv3.y), z3q = pk2(zv3.z, zv3.w);
    fma2(A00, p0p, z0p); fma2(A01, p0p, z1p); fma2(A02, p0p, z2p); fma2(A03, p0p, z3p);
    fma2(A10, p1p, z0p); fma2(A11, p1p, z1p); fma2(A12, p1p, z2p); fma2(A13, p1p, z3p);
    fma2(A00, p0q, z0q); fma2(A01, p0q, z1q); fma2(A02, p0q, z2q); fma2(A03, p0q, z3q);
    fma2(A10, p1q, z0q); fma2(A11, p1q, z1q); fma2(A12, p1q, z2q); fma2(A13, p1q, z3q);
  }
  float b0 = bh[0], b1 = bh[1];
  float e00=__expf(hsum2(A00)+b0), e01=__expf(hsum2(A01)+b0),
        e02=__expf(hsum2(A02)+b0), e03=__expf(hsum2(A03)+b0);
  float e10=__expf(hsum2(A10)+b1), e11=__expf(hsum2(A11)+b1),
        e12=__expf(hsum2(A12)+b1), e13=__expf(hsum2(A13)+b1);
  size_t base0 = ((size_t)(b*HH + 0)*NX + xg)*1024 + yq*32 + zq;
  size_t base1 = ((size_t)(b*HH + 1)*NX + xg)*1024 + yq*32 + zq;
  gatt[base0 +  0] = e00; gatt[base0 +  8] = e01; gatt[base0 + 16] = e02; gatt[base0 + 24] = e03;
  gatt[base1 +  0] = e10; gatt[base1 +  8] = e11; gatt[base1 + 16] = e12; gatt[base1 + 24] = e13;

  float ls0 = e00+e01+e02+e03, ls1 = e10+e11+e12+e13;
  ls0 = warp_sum(ls0); ls1 = warp_sum(ls1);
  int wid = threadIdx.x >> 5;         // 0..15 (0-7 half0, 8-15 half1)
  if ((threadIdx.x & 31) == 0){ sred[wid] = ls0; sred[16 + wid] = ls1; }
  __syncthreads();
  if (threadIdx.x < 32){
    // groups of 8: [h0,half0][h0,half1][h1,half0][h1,half1]
    float v = sred[threadIdx.x];
    v += __shfl_xor_sync(0xffffffffu, v, 1);
    v += __shfl_xor_sync(0xffffffffu, v, 2);
    v += __shfl_xor_sync(0xffffffffu, v, 4);
    if ((threadIdx.x & 7) == 0){
      int h = threadIdx.x >> 4, hf = (threadIdx.x >> 3) & 1;
      d_blocksum[b][h][blockIdx.x*2 + hf] = v;
    }
  }
}

// ---------------- K3: normalize att + logits partials + last-block reduce + BN ----------------
__global__ void __launch_bounds__(512) finalize_kernel(float* __restrict__ gatt,
                                                       const float* __restrict__ gamma,
                                                       const float* __restrict__ beta,
                                                       float* __restrict__ out){
  extern __shared__ float sm[];
  float* sy = sm;              // 8192
  float* sz = sm + 8192;       // 8192
  float* w  = sm + 16384;      // 1024 (att0+att1)
  float* vb = sm + 17408;      // 512
  float* sS = sm + 17920;      // 2
  __shared__ int flag1, flag2;
  int xg = blockIdx.x, b = blockIdx.y;
  int tid = threadIdx.x;
  int yh = tid >> 8, k = tid & 255;

  if (tid < 64){
    int h = tid >> 5, lane = tid & 31;
    float v = d_blocksum[b][h][lane];
    v = warp_sum(v);
    if (lane == 0) sS[h] = 1.f / v;
  }
  const float4* Hy4 = reinterpret_cast<const float4*>(&d_Hbuf[1][b][0][0]);
  const float4* Hz4 = reinterpret_cast<const float4*>(&d_Hbuf[2][b][0][0]);
  float4* sy4 = reinterpret_cast<float4*>(sy);
  float4* sz4 = reinterpret_cast<float4*>(sz);
  for (int i = tid; i < 2048; i += 512){ sy4[i] = Hy4[i]; sz4[i] = Hz4[i]; }
  float xk = d_Hbuf[0][b][xg][k];
  __syncthreads();

  { // normalize att in place + build w = att0+att1 (float2 per thread, 1024 floats total)
    float invS0 = sS[0], invS1 = sS[1];
    float2* g0 = reinterpret_cast<float2*>(gatt + ((size_t)(b*HH + 0)*NX + xg)*1024);
    float2* g1 = reinterpret_cast<float2*>(gatt + ((size_t)(b*HH + 1)*NX + xg)*1024);
    float2 e0 = g0[tid], e1 = g1[tid];
    float2 n0, n1, wv;
    n0.x = e0.x*invS0; n0.y = e0.y*invS0;
    n1.x = e1.x*invS1; n1.y = e1.y*invS1;
    wv.x = n0.x + n1.x; wv.y = n0.y + n1.y;
    g0[tid] = n0; g1[tid] = n1;
    reinterpret_cast<float2*>(w)[tid] = wv;
  }
  __syncthreads();

  ull zk2[16];
#pragma unroll
  for (int zp = 0; zp < 16; zp++)
    zk2[zp] = pk2(sz[(2*zp)*256 + k], sz[(2*zp+1)*256 + k]);

  float v = 0.f;
#pragma unroll 4
  for (int j = 0; j < 16; j++){
    int yy = yh*16 + j;
    const float4* wr = reinterpret_cast<const float4*>(w + yy*32);
    ull t2a = 0ull, t2b = 0ull;
#pragma unroll
    for (int q = 0; q < 8; q++){
      float4 wv = wr[q];
      fma2(t2a, pk2(wv.x, wv.y), zk2[2*q]);
      fma2(t2b, pk2(wv.z, wv.w), zk2[2*q+1]);
    }
    v = fmaf(sy[yy*256 + k], hsum2(add2(t2a, t2b)), v);
  }
  vb[tid] = v;
  __syncthreads();
  if (tid < 256) d_partial[b][xg][k] = xk * (vb[tid] + vb[tid + 256]);
  __threadfence();
  if (tid == 0){
    int old = atomicAdd(&d_cnt_b[b], 1);
    flag1 = (old == 31);
  }
  __syncthreads();
  if (flag1){
    __threadfence();
    { // deterministic x-reduction for this b
      int xh = tid >> 8, kk = tid & 255;
      float s = 0.f;
#pragma unroll
      for (int i = 0; i < 16; i++) s += d_partial[b][xh*16 + i][kk];
      vb[tid] = s;
    }
    __syncthreads();
    if (tid < 256) d_logits[b][tid] = vb[tid] + vb[tid + 256];
    __threadfence();
    __syncthreads();
    if (tid == 0){
      __threadfence();
      int o2 = atomicAdd(&d_cnt_all, 1);
      flag2 = (o2 == 7);
    }
    __syncthreads();
    if (flag2){
      __threadfence();
      if (tid < 256){
        int kk = tid;
        float l[8];
        float mean = 0.f;
#pragma unroll
        for (int b2 = 0; b2 < 8; b2++){ l[b2] = d_logits[b2][kk]; mean += l[b2]; }
        mean *= 0.125f;
        float var = 0.f;
#pragma unroll
        for (int b2 = 0; b2 < 8; b2++){ float d = l[b2] - mean; var = fmaf(d, d, var); }
        var *= 0.125f;
        float inv = rsqrtf(var + 1e-5f);
        float ga = gamma[kk], be = beta[kk];
#pragma unroll
        for (int b2 = 0; b2 < 8; b2++) out[b2*KK + kk] = (l[b2] - mean) * inv * ga + be;
      }
      if (tid == 0){            // reset counters for the next graph replay
        d_cnt_all = 0;
#pragma unroll
        for (int i = 0; i < 8; i++) d_cnt_b[i] = 0;
      }
    }
  }
}

extern "C" void kernel_launch(void* const* d_in, const int* in_sizes, int n_in,
                              void* d_out, int out_size){
  const float* x     = (const float*)d_in[0];
  const float* y     = (const float*)d_in[1];
  const float* z     = (const float*)d_in[2];
  const float* Vx    = (const float*)d_in[3];
  const float* gx    = (const float*)d_in[4];
  const float* bx    = (const float*)d_in[5];
  const float* Vy    = (const float*)d_in[6];
  const float* gy    = (const float*)d_in[7];
  const float* by    = (const float*)d_in[8];
  const float* Vz    = (const float*)d_in[9];
  const float* gz    = (const float*)d_in[10];
  const float* bz    = (const float*)d_in[11];
  const float* Vh    = (const float*)d_in[12];
  const float* gh    = (const float*)d_in[13];
  const float* bh    = (const float*)d_in[14];
  const float* gamma = (const float*)d_in[15];
  const float* beta  = (const float*)d_in[16];

  float* out = (float*)d_out;        // (out [8,256], att [8,2,32,32,32]) flattened in order
  float* att = out + BB*KK;

  const int SMEM2 = (64*SROW + 1024 + 32) * (int)sizeof(float);
  const int SMEM3 = (8192 + 8192 + 1024 + 512 + 2 + 6) * (int)sizeof(float);
  cudaFuncSetAttribute(score_kernel,    cudaFuncAttributeMaxDynamicSharedMemorySize, SMEM2);
  cudaFuncSetAttribute(finalize_kernel, cudaFuncAttributeMaxDynamicSharedMemorySize, SMEM3);

  scale_kernel<<<4, 256>>>(Vx, Vy, Vz, Vh, gx, gy, gz, gh);
  proj_kernel<<<96, 256>>>(x, y, z, Vx, Vy, Vz, bx, by, bz);
  score_kernel<<<dim3(16, BB), 512, SMEM2>>>(Vh, bh, att);
  finalize_kernel<<<dim3(NX, BB), 512, SMEM3>>>(att, gamma, beta, out);
}

// round 11
// speedup vs baseline: 1.3531x; 1.0998x over previous
#include <cuda_runtime.h>

#define BB 8
#define NX 32
#define DD 128
#define KK 256
#define HH 2
#define SROW 260   // padded smem row stride (floats); row = 1040B, 16B-aligned

typedef unsigned long long ull;

__device__ float d_Hbuf[3][BB][NX][KK];     // relu(in@W^T+b) for x,y,z
__device__ float d_blocksum[BB][HH][NX];    // partial exp-sums per (b,h,x)
__device__ float d_partial[BB][NX][KK];     // logits partials per (b,x)
__device__ float d_logits[BB][KK];
__device__ int   d_cnt_b[BB];
__device__ int   d_cnt_all;

__device__ __forceinline__ float warp_sum(float v){
#pragma unroll
  for (int o = 16; o > 0; o >>= 1) v += __shfl_xor_sync(0xffffffffu, v, o);
  return v;
}
__device__ __forceinline__ ull pk2(float lo, float hi){
  ull r; asm("mov.b64 %0, {%1,%2};" : "=l"(r) : "f"(lo), "f"(hi)); return r;
}
__device__ __forceinline__ void fma2(ull& d, ull a, ull b){
  asm("fma.rn.f32x2 %0, %1, %2, %0;" : "+l"(d) : "l"(a), "l"(b));
}
__device__ __forceinline__ ull mul2(ull a, ull b){
  ull r; asm("mul.rn.f32x2 %0, %1, %2;" : "=l"(r) : "l"(a), "l"(b)); return r;
}
__device__ __forceinline__ ull add2(ull a, ull b){
  ull r; asm("add.rn.f32x2 %0, %1, %2;" : "=l"(r) : "l"(a), "l"(b)); return r;
}
__device__ __forceinline__ float hsum2(ull a){
  float lo, hi; asm("mov.b64 {%0,%1}, %2;" : "=f"(lo), "=f"(hi) : "l"(a)); return lo + hi;
}

// ---------------- K1: projections with inline weight-norm; 8 rows/thread ----------------
__global__ void __launch_bounds__(256, 1) proj_kernel(
    const float* __restrict__ x, const float* __restrict__ y, const float* __restrict__ z,
    const float* __restrict__ Vx, const float* __restrict__ Vy, const float* __restrict__ Vz,
    const float* __restrict__ bx, const float* __restrict__ by, const float* __restrict__ bz,
    const float* __restrict__ gx, const float* __restrict__ gy, const float* __restrict__ gz){
  int id = blockIdx.x;               // 96 = b(8) x t(3) x g(4 groups of 8 rows)
  int b = id / 12; int rem = id % 12; int t = rem >> 2; int g = rem & 3;
  const float* in   = (t==0)?x :(t==1)?y :z;
  const float* V    = (t==0)?Vx:(t==1)?Vy:Vz;
  const float* bias = (t==0)?bx:(t==1)?by:bz;
  const float* gs   = (t==0)?gx:(t==1)?gy:gz;
  __shared__ float4 srow[8][32];
  __shared__ float  red[8];
  __shared__ float  sscale;
  int tid = threadIdx.x;
  srow[tid >> 5][tid & 31] =
      reinterpret_cast<const float4*>(in + (size_t)(b*NX + g*8 + (tid>>5))*DD)[tid & 31];
  __syncthreads();
  int k = tid;
  const float4* Vr = reinterpret_cast<const float4*>(V + (size_t)k * DD);
  float acc[8];
#pragma unroll
  for (int r = 0; r < 8; r++) acc[r] = 0.f;
  float vsq = 0.f;
#pragma unroll 4
  for (int d = 0; d < 32; d++){
    float4 v = Vr[d];
    vsq = fmaf(v.x,v.x, fmaf(v.y,v.y, fmaf(v.z,v.z, fmaf(v.w,v.w, vsq))));
#pragma unroll
    for (int r = 0; r < 8; r++){
      float4 p = srow[r][d];
      acc[r] += v.x*p.x + v.y*p.y + v.z*p.z + v.w*p.w;
    }
  }
  vsq = warp_sum(vsq);               // 256 threads cover all 256 k rows exactly once
  if ((tid & 31) == 0) red[tid >> 5] = vsq;
  __syncthreads();
  if (tid < 32){
    float v = (tid < 8) ? red[tid] : 0.f;
    v = warp_sum(v);
    if (tid == 0) sscale = gs[0] * rsqrtf(v);
  }
  __syncthreads();
  float sc = sscale, bk = bias[k];
#pragma unroll
  for (int r = 0; r < 8; r++)
    d_Hbuf[t][b][g*8 + r][k] = fmaxf(fmaf(acc[r], sc, bk), 0.f);
}

// ---------------- K2: scores -> exp (shift=0) -> partial sums; 2 x per block ----------------
__global__ void __launch_bounds__(512) score_kernel(const float* __restrict__ Vh,
                                                    const float* __restrict__ gh,
                                                    const float* __restrict__ bh,
                                                    float* __restrict__ gatt){
  extern __shared__ float sm[];
  float* sy   = sm;                  // 32 rows, stride SROW
  float* sz   = sm + 32*SROW;
  float* sa   = sm + 64*SROW;        // [half][h][256]
  float* sred = sa + 1024;           // 32
  float* ssc  = sred + 32;           // 1
  int b = blockIdx.y;
  int tid = threadIdx.x;
  int half = tid >> 8;
  int xg = blockIdx.x*2 + half;
  int t = tid & 255;

  const float4* Hy4 = reinterpret_cast<const float4*>(&d_Hbuf[1][b][0][0]);
  const float4* Hz4 = reinterpret_cast<const float4*>(&d_Hbuf[2][b][0][0]);
  for (int i = tid; i < 2048; i += 512){
    int row = i >> 6, col = i & 63;
    reinterpret_cast<float4*>(sy + row*SROW)[col] = Hy4[i];
    reinterpret_cast<float4*>(sz + row*SROW)[col] = Hz4[i];
  }
  { // ||Vh||_F over 512 elems, one per thread
    float v = Vh[tid];
    float s = warp_sum(v * v);
    if ((tid & 31) == 0) sred[tid >> 5] = s;
  }
  __syncthreads();
  if (tid == 0){
    float s = 0.f;
#pragma unroll
    for (int i = 0; i < 16; i++) s += sred[i];
    ssc[0] = gh[0] * rsqrtf(s);
  }
  __syncthreads();
  {
    float sh = ssc[0];
    float xv = d_Hbuf[0][b][xg][t];
    sa[half*512 + t]       = xv * sh * Vh[t];
    sa[half*512 + 256 + t] = xv * sh * Vh[KK + t];
  }
  __syncthreads();

  int yq = t >> 3, zq = t & 7;
  const ulonglong2* a04 = reinterpret_cast<const ulonglong2*>(sa + half*512);
  const ulonglong2* a14 = reinterpret_cast<const ulonglong2*>(sa + half*512 + 256);
  const ulonglong2* yr  = reinterpret_cast<const ulonglong2*>(sy + yq*SROW);
  const ulonglong2* z0r = reinterpret_cast<const ulonglong2*>(sz + (zq +  0)*SROW);
  const ulonglong2* z1r = reinterpret_cast<const ulonglong2*>(sz + (zq +  8)*SROW);
  const ulonglong2* z2r = reinterpret_cast<const ulonglong2*>(sz + (zq + 16)*SROW);
  const ulonglong2* z3r = reinterpret_cast<const ulonglong2*>(sz + (zq + 24)*SROW);

  ull A00=0ull,A01=0ull,A02=0ull,A03=0ull,A10=0ull,A11=0ull,A12=0ull,A13=0ull;
#pragma unroll 4
  for (int kb = 0; kb < 64; kb++){
    ulonglong2 aa0 = a04[kb], aa1 = a14[kb], yy2 = yr[kb];
    ulonglong2 zz0 = z0r[kb], zz1 = z1r[kb], zz2 = z2r[kb], zz3 = z3r[kb];
    ull p0l = mul2(aa0.x, yy2.x), p0h = mul2(aa0.y, yy2.y);
    ull p1l = mul2(aa1.x, yy2.x), p1h = mul2(aa1.y, yy2.y);
    fma2(A00, p0l, zz0.x); fma2(A01, p0l, zz1.x); fma2(A02, p0l, zz2.x); fma2(A03, p0l, zz3.x);
    fma2(A10, p1l, zz0.x); fma2(A11, p1l, zz1.x); fma2(A12, p1l, zz2.x); fma2(A13, p1l, zz3.x);
    fma2(A00, p0h, zz0.y); fma2(A01, p0h, zz1.y); fma2(A02, p0h, zz2.y); fma2(A03, p0h, zz3.y);
    fma2(A10, p1h, zz0.y); fma2(A11, p1h, zz1.y); fma2(A12, p1h, zz2.y); fma2(A13, p1h, zz3.y);
  }
  float b0 = bh[0], b1 = bh[1];
  float e00=__expf(hsum2(A00)+b0), e01=__expf(hsum2(A01)+b0),
        e02=__expf(hsum2(A02)+b0), e03=__expf(hsum2(A03)+b0);
  float e10=__expf(hsum2(A10)+b1), e11=__expf(hsum2(A11)+b1),
        e12=__expf(hsum2(A12)+b1), e13=__expf(hsum2(A13)+b1);
  size_t base0 = ((size_t)(b*HH + 0)*NX + xg)*1024 + yq*32 + zq;
  size_t base1 = ((size_t)(b*HH + 1)*NX + xg)*1024 + yq*32 + zq;
  gatt[base0 +  0] = e00; gatt[base0 +  8] = e01; gatt[base0 + 16] = e02; gatt[base0 + 24] = e03;
  gatt[base1 +  0] = e10; gatt[base1 +  8] = e11; gatt[base1 + 16] = e12; gatt[base1 + 24] = e13;

  float ls0 = e00+e01+e02+e03, ls1 = e10+e11+e12+e13;
  ls0 = warp_sum(ls0); ls1 = warp_sum(ls1);
  int wid = tid >> 5;                 // 0..15 (0-7 half0, 8-15 half1)
  if ((tid & 31) == 0){ sred[wid] = ls0; sred[16 + wid] = ls1; }
  __syncthreads();
  if (tid < 32){
    // groups of 8: [h0,half0][h0,half1][h1,half0][h1,half1]
    float v = sred[tid];
    v += __shfl_xor_sync(0xffffffffu, v, 1);
    v += __shfl_xor_sync(0xffffffffu, v, 2);
    v += __shfl_xor_sync(0xffffffffu, v, 4);
    if ((tid & 7) == 0){
      int h = tid >> 4, hf = (tid >> 3) & 1;
      d_blocksum[b][h][blockIdx.x*2 + hf] = v;
    }
  }
}

// ---------------- K3: normalize att + logits partials + last-block reduce + BN; 2 x per block ----------------
__global__ void __launch_bounds__(512) finalize_kernel(float* __restrict__ gatt,
                                                       const float* __restrict__ gamma,
                                                       const float* __restrict__ beta,
                                                       float* __restrict__ out){
  extern __shared__ float sm[];
  float* sy = sm;              // 8192 (unpadded: k is thread-contiguous)
  float* sz = sm + 8192;       // 8192
  float* w  = sm + 16384;      // 2048: [half][1024] att0+att1 (reused as BN scratch)
  float* sS = sm + 18432;      // 2
  __shared__ int flag1, flag2;
  int b = blockIdx.y, bx = blockIdx.x;
  int tid = threadIdx.x;
  int half = tid >> 8, k = tid & 255;
  int xg = bx*2 + half;

  if (tid < 64){
    int h = tid >> 5, lane = tid & 31;
    float v = d_blocksum[b][h][lane];
    v = warp_sum(v);
    if (lane == 0) sS[h] = 1.f / v;
  }
  const float4* Hy4 = reinterpret_cast<const float4*>(&d_Hbuf[1][b][0][0]);
  const float4* Hz4 = reinterpret_cast<const float4*>(&d_Hbuf[2][b][0][0]);
  float4* sy4 = reinterpret_cast<float4*>(sy);
  float4* sz4 = reinterpret_cast<float4*>(sz);
  for (int i = tid; i < 2048; i += 512){ sy4[i] = Hy4[i]; sz4[i] = Hz4[i]; }
  float xk = d_Hbuf[0][b][xg][k];
  __syncthreads();

  { // normalize att in place + build w = att0+att1; k (0..255) x float4 covers this x's 1024
    float invS0 = sS[0], invS1 = sS[1];
    float4* g0 = reinterpret_cast<float4*>(gatt + ((size_t)(b*HH + 0)*NX + xg)*1024);
    float4* g1 = reinterpret_cast<float4*>(gatt + ((size_t)(b*HH + 1)*NX + xg)*1024);
    float4 e0 = g0[k], e1 = g1[k];
    float4 n0, n1, wv;
    n0.x=e0.x*invS0; n0.y=e0.y*invS0; n0.z=e0.z*invS0; n0.w=e0.w*invS0;
    n1.x=e1.x*invS1; n1.y=e1.y*invS1; n1.z=e1.z*invS1; n1.w=e1.w*invS1;
    wv.x=n0.x+n1.x; wv.y=n0.y+n1.y; wv.z=n0.z+n1.z; wv.w=n0.w+n1.w;
    g0[k] = n0; g1[k] = n1;
    reinterpret_cast<float4*>(w + half*1024)[k] = wv;
  }
  __syncthreads();

  ull zk2[16];
#pragma unroll
  for (int zp = 0; zp < 16; zp++)
    zk2[zp] = pk2(sz[(2*zp)*256 + k], sz[(2*zp+1)*256 + k]);

  float v = 0.f;
#pragma unroll 4
  for (int yy = 0; yy < 32; yy++){
    const ulonglong2* wr = reinterpret_cast<const ulonglong2*>(w + half*1024 + yy*32);
    ull t2a = 0ull, t2b = 0ull;
#pragma unroll
    for (int q = 0; q < 8; q++){
      ulonglong2 wv = wr[q];
      fma2(t2a, wv.x, zk2[2*q]);
      fma2(t2b, wv.y, zk2[2*q+1]);
    }
    v = fmaf(sy[yy*256 + k], hsum2(add2(t2a, t2b)), v);
  }
  d_partial[b][xg][k] = xk * v;
  __threadfence();
  __syncthreads();
  if (tid == 0){
    int old = atomicAdd(&d_cnt_b[b], 1);
    flag1 = (old == 15);
  }
  __syncthreads();
  if (flag1){                      // last block of this b: deterministic x-reduction
    __threadfence();
    {
      int xh2 = tid >> 8, kk = tid & 255;
      float s = 0.f;
#pragma unroll
      for (int i = 0; i < 16; i++) s += d_partial[b][xh2*16 + i][kk];
      w[tid] = s;
    }
    __syncthreads();
    if (tid < 256) d_logits[b][tid] = w[tid] + w[tid + 256];
    __threadfence();
    __syncthreads();
    if (tid == 0){
      int o2 = atomicAdd(&d_cnt_all, 1);
      flag2 = (o2 == 7);
    }
    __syncthreads();
    if (flag2){                    // globally last block: BatchNorm
      __threadfence();
      if (tid < 256){
        int kk = tid;
        float l[8];
        float mean = 0.f;
#pragma unroll
        for (int b2 = 0; b2 < 8; b2++){ l[b2] = d_logits[b2][kk]; mean += l[b2]; }
        mean *= 0.125f;
        float var = 0.f;
#pragma unroll
        for (int b2 = 0; b2 < 8; b2++){ float d = l[b2] - mean; var = fmaf(d, d, var); }
        var *= 0.125f;
        float inv = rsqrtf(var + 1e-5f);
        float ga = gamma[kk], be = beta[kk];
#pragma unroll
        for (int b2 = 0; b2 < 8; b2++) out[b2*KK + kk] = (l[b2] - mean) * inv * ga + be;
      }
      if (tid == 0){               // reset counters for next graph replay
        d_cnt_all = 0;
#pragma unroll
        for (int i = 0; i < 8; i++) d_cnt_b[i] = 0;
      }
    }
  }
}

extern "C" void kernel_launch(void* const* d_in, const int* in_sizes, int n_in,
                              void* d_out, int out_size){
  const float* x     = (const float*)d_in[0];
  const float* y     = (const float*)d_in[1];
  const float* z     = (const float*)d_in[2];
  const float* Vx    = (const float*)d_in[3];
  const float* gx    = (const float*)d_in[4];
  const float* bx    = (const float*)d_in[5];
  const float* Vy    = (const float*)d_in[6];
  const float* gy    = (const float*)d_in[7];
  const float* by    = (const float*)d_in[8];
  const float* Vz    = (const float*)d_in[9];
  const float* gz    = (const float*)d_in[10];
  const float* bz    = (const float*)d_in[11];
  const float* Vh    = (const float*)d_in[12];
  const float* gh    = (const float*)d_in[13];
  const float* bh    = (const float*)d_in[14];
  const float* gamma = (const float*)d_in[15];
  const float* beta  = (const float*)d_in[16];

  float* out = (float*)d_out;        // (out [8,256], att [8,2,32,32,32]) flattened in order
  float* att = out + BB*KK;

  const int SMEM2 = (64*SROW + 1024 + 32 + 4) * (int)sizeof(float);
  const int SMEM3 = (8192 + 8192 + 2048 + 2 + 6) * (int)sizeof(float);
  cudaFuncSetAttribute(score_kernel,    cudaFuncAttributeMaxDynamicSharedMemorySize, SMEM2);
  cudaFuncSetAttribute(finalize_kernel, cudaFuncAttributeMaxDynamicSharedMemorySize, SMEM3);

  proj_kernel<<<96, 256>>>(x, y, z, Vx, Vy, Vz, bx, by, bz, gx, gy, gz);
  score_kernel<<<dim3(16, BB), 512, SMEM2>>>(Vh, gh, bh, att);
  finalize_kernel<<<dim3(16, BB), 512, SMEM3>>>(att, gamma, beta, out);
}